// round 10
// baseline (speedup 1.0000x reference)
#include <cuda_runtime.h>

#define Bx 4
#define Nn 2048
#define Dd 512
#define Hh 8
#define NC 4       // node chunks for k_z
#define NPC 512    // nodes per chunk

// ---------------- device scratch ----------------
__device__ float g_u[Hh][Dd];
__device__ float g_ch[Hh];
__device__ float g_s0p[Hh][8];
__device__ float g_sc[Bx][Hh][Nn];         // node scores
__device__ float g_nm[Bx][Hh];             // softmax max
__device__ float g_nrs[Bx][Hh];            // softmax 1/sum
__device__ float g_p0[Bx][Hh];             // CLS probability
__device__ float g_zp[NC][Bx][Hh][Dd];     // p-weighted z partials (256 KB)
__device__ float g_w[Bx][Dd];
__device__ float g_y[Bx][Dd];

__device__ __forceinline__ float warp_sum(float v) {
    #pragma unroll
    for (int o = 16; o; o >>= 1) v += __shfl_xor_sync(0xffffffffu, v, o);
    return v;
}
__device__ __forceinline__ float warp_max(float v) {
    #pragma unroll
    for (int o = 16; o; o >>= 1) v = fmaxf(v, __shfl_xor_sync(0xffffffffu, v, o));
    return v;
}
__device__ __forceinline__ float dot4(float4 a, float4 b) {
    return a.x * b.x + a.y * b.y + a.z * b.z + a.w * b.w;
}

// ============ k_prep: per (head, d-chunk): q0 slice, u, s0 partials, ch ============
// grid (Hh, 8), 512 threads
__global__ void k_prep(const float* __restrict__ Wq, const float* __restrict__ bq,
                       const float* __restrict__ Wk, const float* __restrict__ bk,
                       const float* __restrict__ ct) {
    const int h = blockIdx.x, dc = blockIdx.y;
    const int t = threadIdx.x, wid = t >> 5, lane = t & 31;
    __shared__ __align__(16) float cts[Dd];
    __shared__ float q0s[64], red8[8][64], red64[64];
    cts[t] = ct[t];
    __syncthreads();
    {   // q0 slice for head h: 16 warps x 4 rows
        const float4* cv = (const float4*)cts;
        #pragma unroll
        for (int rr = 0; rr < 4; rr++) {
            const int i = wid + rr * 16;
            const float4* row = (const float4*)(Wq + (size_t)(h * 64 + i) * Dd);
            float s = 0.f;
            #pragma unroll
            for (int k = 0; k < 4; k++) s += dot4(row[lane + 32 * k], cv[lane + 32 * k]);
            s = warp_sum(s);
            if (lane == 0) q0s[i] = s + bq[h * 64 + i];
        }
    }
    __syncthreads();
    const int part8 = t >> 6, dl = t & 63;
    {
        const float* base = Wk + (size_t)(h * 64 + part8 * 8) * Dd + dc * 64 + dl;
        float acc = 0.f;
        #pragma unroll
        for (int i = 0; i < 8; i++) acc += q0s[part8 * 8 + i] * base[(size_t)i * Dd];
        red8[part8][dl] = acc;
    }
    __syncthreads();
    if (t < 64) {
        float u = 0.f;
        #pragma unroll
        for (int p = 0; p < 8; p++) u += red8[p][t];
        g_u[h][dc * 64 + t] = u;
        red64[t] = u * cts[dc * 64 + t];
    }
    __syncthreads();
    if (t < 32) {
        float v = red64[t] + red64[t + 32];
        v = warp_sum(v);
        if (t == 0) g_s0p[h][dc] = v;
        if (dc == 0) {
            float cvv = q0s[t] * bk[h * 64 + t] + q0s[t + 32] * bk[h * 64 + t + 32];
            cvv = warp_sum(cvv);
            if (t == 0) g_ch[h] = cvv;
        }
    }
}

// ============ k_scores: warp = 2 node rows (MLP 8), all 8 heads ============
// grid (Nn/16, Bx), 256 threads
__global__ void k_scores(const float* __restrict__ nf, const float* __restrict__ masks) {
    __shared__ __align__(16) float4 us4[Hh * 128];   // 16 KB
    __shared__ float chs[Hh];
    const int b = blockIdx.y;
    const int t = threadIdx.x, wid = t >> 5, lane = t & 31;
    {
        const float4* uf = (const float4*)&g_u[0][0];
        #pragma unroll
        for (int k = 0; k < 4; k++) us4[t + k * 256] = uf[t + k * 256];
        if (t < Hh) chs[t] = g_ch[t];
    }
    __syncthreads();
    const int n0 = blockIdx.x * 16 + wid * 2;
    const float4* x4 = (const float4*)(nf + ((size_t)b * Nn + n0) * Dd);
    float4 xr0[4], xr1[4];
    #pragma unroll
    for (int k = 0; k < 4; k++) { xr0[k] = x4[lane + 32 * k]; xr1[k] = x4[128 + lane + 32 * k]; }
    const float mv0 = masks[(size_t)b * Nn + n0];
    const float mv1 = masks[(size_t)b * Nn + n0 + 1];
    #pragma unroll
    for (int h = 0; h < Hh; h++) {
        float s0 = 0.f, s1 = 0.f;
        #pragma unroll
        for (int k = 0; k < 4; k++) {
            const float4 uv = us4[h * 128 + lane + 32 * k];
            s0 += dot4(uv, xr0[k]);
            s1 += dot4(uv, xr1[k]);
        }
        s0 = warp_sum(s0);
        s1 = warp_sum(s1);
        if (lane == 0) {
            float v0 = (s0 + chs[h]) * 0.125f;
            float v1 = (s1 + chs[h]) * 0.125f;
            if (mv0 * mv0 == 0.f) v0 = -1e9f;
            if (mv1 * mv1 == 0.f) v1 = -1e9f;
            g_sc[b][h][n0] = v0;
            g_sc[b][h][n0 + 1] = v1;
        }
    }
}

// ============ k_softmax: per (b,h) -> (M, 1/S, p0). grid 32, 1024 thr ============
__global__ void k_softmax() {
    const int b = blockIdx.x >> 3, h = blockIdx.x & 7;
    const int t = threadIdx.x, wid = t >> 5, lane = t & 31;
    __shared__ float red[32];
    __shared__ float Msh, s0sh;
    const float v0 = g_sc[b][h][t], v1 = g_sc[b][h][t + 1024];
    float m = warp_max(fmaxf(v0, v1));
    if (lane == 0) red[wid] = m;
    __syncthreads();
    if (wid == 0) {
        float x = warp_max(red[lane]);
        if (lane == 0) {
            float sp = 0.f;
            #pragma unroll
            for (int dc = 0; dc < 8; dc++) sp += g_s0p[h][dc];
            const float s0 = (sp + g_ch[h]) * 0.125f;
            s0sh = s0;
            Msh = fmaxf(x, s0);
        }
    }
    __syncthreads();
    const float M = Msh;
    float e = expf(v0 - M) + expf(v1 - M);
    e = warp_sum(e);
    if (lane == 0) red[wid] = e;
    __syncthreads();
    if (wid == 0) {
        float x = warp_sum(red[lane]);
        if (lane == 0) {
            const float S = x + expf(s0sh - M);
            g_nm[b][h] = M;
            g_nrs[b][h] = 1.f / S;
            g_p0[b][h] = expf(s0sh - M) / S;
        }
    }
}

// ============ k_z: grid (Bx, 8 d-chunks, NC node-chunks), 256 thr ============
// Each block: 512 nodes x 64 dims, all 8 heads. Writes tiny partials.
__global__ void k_z(const float* __restrict__ nf) {
    const int b = blockIdx.x, dc = blockIdx.y, nc = blockIdx.z;
    const int t = threadIdx.x;
    __shared__ float ps[Hh][NPC];        // 16 KB
    __shared__ float red[NC][Hh][64];    // 8 KB
    const int n0 = nc * NPC;
    // stage probabilities for 512 nodes x 8 heads
    #pragma unroll
    for (int idx = t; idx < Hh * NPC; idx += 256) {
        const int h = idx >> 9, jj = idx & 511;
        ps[h][jj] = expf(g_sc[b][h][n0 + jj] - g_nm[b][h]) * g_nrs[b][h];
    }
    __syncthreads();
    const int dl = t & 63, npar = t >> 6;   // 4 node-parallel groups of 128 nodes
    float acc[Hh];
    #pragma unroll
    for (int h = 0; h < Hh; h++) acc[h] = 0.f;
    const float* xp = nf + ((size_t)b * Nn + n0 + npar * 128) * Dd + dc * 64 + dl;
    const float* pp = &ps[0][npar * 128];
    #pragma unroll 4
    for (int jj = 0; jj < 128; jj++) {
        const float xv = xp[(size_t)jj * Dd];
        #pragma unroll
        for (int h = 0; h < Hh; h++) acc[h] += pp[h * NPC + jj] * xv;
    }
    #pragma unroll
    for (int h = 0; h < Hh; h++) red[npar][h][dl] = acc[h];
    __syncthreads();
    #pragma unroll
    for (int idx = t; idx < Hh * 64; idx += 256) {
        const int h = idx >> 6, d = idx & 63;
        g_zp[nc][b][h][dc * 64 + d] = red[0][h][d] + red[1][h][d] + red[2][h][d] + red[3][h][d];
    }
}

// ============ k_wv: grid (Hh, 8 rowgroups), 256 thr. All batches per block ============
__global__ void k_wv(const float* __restrict__ ct, const float* __restrict__ Wv,
                     const float* __restrict__ bv) {
    const int h = blockIdx.x, rg = blockIdx.y;
    const int t = threadIdx.x, wid = t >> 5, lane = t & 31;
    __shared__ __align__(16) float zs[Bx][Dd];   // 8 KB
    #pragma unroll
    for (int idx = t; idx < Bx * Dd; idx += 256) {
        const int b = idx >> 9, d = idx & 511;
        float acc = g_p0[b][h] * ct[d];
        #pragma unroll
        for (int nc = 0; nc < NC; nc++) acc += g_zp[nc][b][h][d];
        zs[b][d] = acc;
    }
    __syncthreads();
    const int i = h * 64 + rg * 8 + wid;
    const float4* row = (const float4*)(Wv + (size_t)i * Dd);
    float4 rv[4];
    #pragma unroll
    for (int k = 0; k < 4; k++) rv[k] = row[lane + 32 * k];
    #pragma unroll
    for (int b = 0; b < Bx; b++) {
        float s = 0.f;
        #pragma unroll
        for (int k = 0; k < 4; k++) s += dot4(rv[k], ((const float4*)zs[b])[lane + 32 * k]);
        s = warp_sum(s);
        if (lane == 0) g_w[b][i] = s + bv[i];
    }
}

// ============ k_wo: warp = (row, batch). grid 256, 256 thr ============
__global__ void k_wo(const float* __restrict__ Wo, const float* __restrict__ bo,
                     const float* __restrict__ ct) {
    __shared__ __align__(16) float4 ws4[Bx * 128];   // 8 KB
    const int t = threadIdx.x, wid = t >> 5, lane = t & 31;
    {
        const float4* gw4 = (const float4*)&g_w[0][0];
        ws4[t] = gw4[t];
        ws4[t + 256] = gw4[t + 256];
    }
    __syncthreads();
    const int gw = blockIdx.x * 8 + wid;
    const int r = gw >> 2, b = gw & 3;
    const float4* row = (const float4*)(Wo + (size_t)r * Dd);
    float s = 0.f;
    #pragma unroll
    for (int k = 0; k < 4; k++) s += dot4(row[lane + 32 * k], ws4[b * 128 + lane + 32 * k]);
    s = warp_sum(s);
    if (lane == 0) g_y[b][r] = s + bo[r] + ct[r];
}

// ============ k_ln: LayerNorm CLS row. grid Bx, 512 thr ============
__global__ void k_ln(const float* __restrict__ gamma, const float* __restrict__ beta,
                     float* __restrict__ out) {
    const int b = blockIdx.x, t = threadIdx.x;
    __shared__ float red[512];
    const float y = g_y[b][t];
    red[t] = y; __syncthreads();
    for (int o = 256; o; o >>= 1) { if (t < o) red[t] += red[t + o]; __syncthreads(); }
    const float mu = red[0] * (1.f / Dd);
    __syncthreads();
    const float dy = y - mu;
    red[t] = dy * dy; __syncthreads();
    for (int o = 256; o; o >>= 1) { if (t < o) red[t] += red[t + o]; __syncthreads(); }
    const float rs = rsqrtf(red[0] * (1.f / Dd) + 1e-5f);
    out[(size_t)b * Dd + t] = dy * rs * gamma[t] + beta[t];
}

// ---------------- launcher ----------------
extern "C" void kernel_launch(void* const* d_in, const int* in_sizes, int n_in,
                              void* d_out, int out_size) {
    const float* nf    = (const float*)d_in[0];
    // d_in[1] edge_weights, d_in[2] adj_matrix: dead for CLS-row output
    const float* masks = (const float*)d_in[3];
    const float* ct    = (const float*)d_in[4];
    const float* Wq    = (const float*)d_in[5];
    const float* bq    = (const float*)d_in[6];
    const float* Wk    = (const float*)d_in[7];
    const float* bk    = (const float*)d_in[8];
    const float* Wv    = (const float*)d_in[9];
    const float* bv    = (const float*)d_in[10];
    const float* Wo    = (const float*)d_in[11];
    const float* bo    = (const float*)d_in[12];
    const float* gamma = (const float*)d_in[13];
    const float* beta  = (const float*)d_in[14];
    float* out = (float*)d_out;

    k_prep   <<<dim3(Hh, 8), 512>>>(Wq, bq, Wk, bk, ct);
    k_scores <<<dim3(Nn / 16, Bx), 256>>>(nf, masks);
    k_softmax<<<32, 1024>>>();
    k_z      <<<dim3(Bx, 8, NC), 256>>>(nf);
    k_wv     <<<dim3(Hh, 8), 256>>>(ct, Wv, bv);
    k_wo     <<<256, 256>>>(Wo, bo, ct);
    k_ln     <<<Bx, 512>>>(gamma, beta, out);
}

// round 11
// speedup vs baseline: 1.1151x; 1.1151x over previous
#include <cuda_runtime.h>

#define Bx 4
#define Nn 2048
#define Dd 512
#define Hh 8
#define ZCH 128    // z chunks
#define ZR  16     // rows per z chunk

// ---------------- device scratch ----------------
__device__ float g_u[Hh][Dd];
__device__ float g_ch[Hh];
__device__ float g_s0p[Hh][8];
__device__ float g_sc[Bx][Hh][Nn];         // node scores
__device__ float g_nm[Bx][Hh];             // softmax max
__device__ float g_nrs[Bx][Hh];            // softmax 1/sum
__device__ float g_p0[Bx][Hh];             // CLS probability
__device__ float g_zp[ZCH][Bx][Hh][Dd];    // p-weighted z partials
__device__ float g_z[Bx][Hh][Dd];          // reduced z
__device__ float g_w[Bx][Dd];
__device__ float g_y[Bx][Dd];

__device__ __forceinline__ float warp_sum(float v) {
    #pragma unroll
    for (int o = 16; o; o >>= 1) v += __shfl_xor_sync(0xffffffffu, v, o);
    return v;
}
__device__ __forceinline__ float warp_max(float v) {
    #pragma unroll
    for (int o = 16; o; o >>= 1) v = fmaxf(v, __shfl_xor_sync(0xffffffffu, v, o));
    return v;
}
__device__ __forceinline__ float dot4(float4 a, float4 b) {
    return a.x * b.x + a.y * b.y + a.z * b.z + a.w * b.w;
}

// ============ k_prep: per (head, d-chunk): q0 slice, u, s0 partials, ch ============
// grid (Hh, 8), 512 threads
__global__ void k_prep(const float* __restrict__ Wq, const float* __restrict__ bq,
                       const float* __restrict__ Wk, const float* __restrict__ bk,
                       const float* __restrict__ ct) {
    const int h = blockIdx.x, dc = blockIdx.y;
    const int t = threadIdx.x, wid = t >> 5, lane = t & 31;
    __shared__ __align__(16) float cts[Dd];
    __shared__ float q0s[64], red8[8][64], red64[64];
    cts[t] = ct[t];
    __syncthreads();
    {   // q0 slice for head h: 16 warps x 4 rows
        const float4* cv = (const float4*)cts;
        #pragma unroll
        for (int rr = 0; rr < 4; rr++) {
            const int i = wid + rr * 16;
            const float4* row = (const float4*)(Wq + (size_t)(h * 64 + i) * Dd);
            float s = 0.f;
            #pragma unroll
            for (int k = 0; k < 4; k++) s += dot4(row[lane + 32 * k], cv[lane + 32 * k]);
            s = warp_sum(s);
            if (lane == 0) q0s[i] = s + bq[h * 64 + i];
        }
    }
    __syncthreads();
    const int part8 = t >> 6, dl = t & 63;
    {
        const float* base = Wk + (size_t)(h * 64 + part8 * 8) * Dd + dc * 64 + dl;
        float acc = 0.f;
        #pragma unroll
        for (int i = 0; i < 8; i++) acc += q0s[part8 * 8 + i] * base[(size_t)i * Dd];
        red8[part8][dl] = acc;
    }
    __syncthreads();
    if (t < 64) {
        float u = 0.f;
        #pragma unroll
        for (int p = 0; p < 8; p++) u += red8[p][t];
        g_u[h][dc * 64 + t] = u;
        red64[t] = u * cts[dc * 64 + t];
    }
    __syncthreads();
    if (t < 32) {
        float v = red64[t] + red64[t + 32];
        v = warp_sum(v);
        if (t == 0) g_s0p[h][dc] = v;
        if (dc == 0) {
            float cvv = q0s[t] * bk[h * 64 + t] + q0s[t + 32] * bk[h * 64 + t + 32];
            cvv = warp_sum(cvv);
            if (t == 0) g_ch[h] = cvv;
        }
    }
}

// ============ k_scores: warp = 2 node rows (MLP 8), all 8 heads ============
// grid (Nn/16, Bx), 256 threads
__global__ void k_scores(const float* __restrict__ nf, const float* __restrict__ masks) {
    __shared__ __align__(16) float4 us4[Hh * 128];   // 16 KB
    __shared__ float chs[Hh];
    const int b = blockIdx.y;
    const int t = threadIdx.x, wid = t >> 5, lane = t & 31;
    {
        const float4* uf = (const float4*)&g_u[0][0];
        #pragma unroll
        for (int k = 0; k < 4; k++) us4[t + k * 256] = uf[t + k * 256];
        if (t < Hh) chs[t] = g_ch[t];
    }
    __syncthreads();
    const int n0 = blockIdx.x * 16 + wid * 2;
    const float4* x4 = (const float4*)(nf + ((size_t)b * Nn + n0) * Dd);
    float4 xr0[4], xr1[4];
    #pragma unroll
    for (int k = 0; k < 4; k++) { xr0[k] = x4[lane + 32 * k]; xr1[k] = x4[128 + lane + 32 * k]; }
    const float mv0 = masks[(size_t)b * Nn + n0];
    const float mv1 = masks[(size_t)b * Nn + n0 + 1];
    #pragma unroll
    for (int h = 0; h < Hh; h++) {
        float s0 = 0.f, s1 = 0.f;
        #pragma unroll
        for (int k = 0; k < 4; k++) {
            const float4 uv = us4[h * 128 + lane + 32 * k];
            s0 += dot4(uv, xr0[k]);
            s1 += dot4(uv, xr1[k]);
        }
        s0 = warp_sum(s0);
        s1 = warp_sum(s1);
        if (lane == 0) {
            float v0 = (s0 + chs[h]) * 0.125f;
            float v1 = (s1 + chs[h]) * 0.125f;
            if (mv0 * mv0 == 0.f) v0 = -1e9f;
            if (mv1 * mv1 == 0.f) v1 = -1e9f;
            g_sc[b][h][n0] = v0;
            g_sc[b][h][n0 + 1] = v1;
        }
    }
}

// ============ k_softmax: per (b,h) -> (M, 1/S, p0). grid 32, 1024 thr ============
__global__ void k_softmax() {
    const int b = blockIdx.x >> 3, h = blockIdx.x & 7;
    const int t = threadIdx.x, wid = t >> 5, lane = t & 31;
    __shared__ float red[32];
    __shared__ float Msh, s0sh;
    const float v0 = g_sc[b][h][t], v1 = g_sc[b][h][t + 1024];
    float m = warp_max(fmaxf(v0, v1));
    if (lane == 0) red[wid] = m;
    __syncthreads();
    if (wid == 0) {
        float x = warp_max(red[lane]);
        if (lane == 0) {
            float sp = 0.f;
            #pragma unroll
            for (int dc = 0; dc < 8; dc++) sp += g_s0p[h][dc];
            const float s0 = (sp + g_ch[h]) * 0.125f;
            s0sh = s0;
            Msh = fmaxf(x, s0);
        }
    }
    __syncthreads();
    const float M = Msh;
    float e = expf(v0 - M) + expf(v1 - M);
    e = warp_sum(e);
    if (lane == 0) red[wid] = e;
    __syncthreads();
    if (wid == 0) {
        float x = warp_sum(red[lane]);
        if (lane == 0) {
            const float S = x + expf(s0sh - M);
            g_nm[b][h] = M;
            g_nrs[b][h] = 1.f / S;
            g_p0[b][h] = expf(s0sh - M) / S;
        }
    }
}

// ============ k_z: final-p-weighted partials; 16 rows, float2 dims ============
// grid (ZCH, Bx), 256 threads
__global__ void k_z(const float* __restrict__ nf) {
    const int c = blockIdx.x, b = blockIdx.y;
    const int t = threadIdx.x;
    __shared__ float ps[Hh][ZR];
    if (t < Hh * ZR) {
        const int h = t >> 4, jj = t & 15;
        ps[h][jj] = expf(g_sc[b][h][c * ZR + jj] - g_nm[b][h]) * g_nrs[b][h];
    }
    __syncthreads();
    float2 acc[Hh];
    #pragma unroll
    for (int h = 0; h < Hh; h++) acc[h] = make_float2(0.f, 0.f);
    const float2* xp = (const float2*)(nf + ((size_t)b * Nn + c * ZR) * Dd) + t;
    #pragma unroll
    for (int jj = 0; jj < ZR; jj++) {
        const float2 xv = xp[jj * 256];
        #pragma unroll
        for (int h = 0; h < Hh; h++) {
            const float p = ps[h][jj];
            acc[h].x += p * xv.x;
            acc[h].y += p * xv.y;
        }
    }
    #pragma unroll
    for (int h = 0; h < Hh; h++)
        ((float2*)&g_zp[c][b][h][0])[t] = acc[h];
}

// ============ k_red: reduce chunk partials. grid (Bx, Hh, 4), 128 thr ============
__global__ void k_red(const float* __restrict__ ct) {
    const int b = blockIdx.x, h = blockIdx.y, q = blockIdx.z;
    const int d = q * 128 + threadIdx.x;
    float acc = g_p0[b][h] * ct[d];
    #pragma unroll 8
    for (int c = 0; c < ZCH; c++) acc += g_zp[c][b][h][d];
    g_z[b][h][d] = acc;
}

// ============ k_wv: grid (Hh, 8 rowgroups), 256 thr. Wv read once ============
__global__ void k_wv(const float* __restrict__ Wv, const float* __restrict__ bv) {
    const int h = blockIdx.x, rg = blockIdx.y;
    const int t = threadIdx.x, wid = t >> 5, lane = t & 31;
    __shared__ __align__(16) float zs[Bx][Dd];   // 8 KB
    #pragma unroll
    for (int idx = t; idx < Bx * Dd; idx += 256) {
        const int b = idx >> 9, d = idx & 511;
        zs[b][d] = g_z[b][h][d];
    }
    __syncthreads();
    const int i = h * 64 + rg * 8 + wid;
    const float4* row = (const float4*)(Wv + (size_t)i * Dd);
    float4 rv[4];
    #pragma unroll
    for (int k = 0; k < 4; k++) rv[k] = row[lane + 32 * k];
    #pragma unroll
    for (int b = 0; b < Bx; b++) {
        float s = 0.f;
        #pragma unroll
        for (int k = 0; k < 4; k++) s += dot4(rv[k], ((const float4*)zs[b])[lane + 32 * k]);
        s = warp_sum(s);
        if (lane == 0) g_w[b][i] = s + bv[i];
    }
}

// ============ k_wo: warp = (row, batch). grid 256, 256 thr ============
__global__ void k_wo(const float* __restrict__ Wo, const float* __restrict__ bo,
                     const float* __restrict__ ct) {
    __shared__ __align__(16) float4 ws4[Bx * 128];   // 8 KB
    const int t = threadIdx.x, wid = t >> 5, lane = t & 31;
    {
        const float4* gw4 = (const float4*)&g_w[0][0];
        ws4[t] = gw4[t];
        ws4[t + 256] = gw4[t + 256];
    }
    __syncthreads();
    const int gw = blockIdx.x * 8 + wid;
    const int r = gw >> 2, b = gw & 3;
    const float4* row = (const float4*)(Wo + (size_t)r * Dd);
    float s = 0.f;
    #pragma unroll
    for (int k = 0; k < 4; k++) s += dot4(row[lane + 32 * k], ws4[b * 128 + lane + 32 * k]);
    s = warp_sum(s);
    if (lane == 0) g_y[b][r] = s + bo[r] + ct[r];
}

// ============ k_ln: LayerNorm CLS row. grid Bx, 512 thr ============
__global__ void k_ln(const float* __restrict__ gamma, const float* __restrict__ beta,
                     float* __restrict__ out) {
    const int b = blockIdx.x, t = threadIdx.x;
    __shared__ float red[512];
    const float y = g_y[b][t];
    red[t] = y; __syncthreads();
    for (int o = 256; o; o >>= 1) { if (t < o) red[t] += red[t + o]; __syncthreads(); }
    const float mu = red[0] * (1.f / Dd);
    __syncthreads();
    const float dy = y - mu;
    red[t] = dy * dy; __syncthreads();
    for (int o = 256; o; o >>= 1) { if (t < o) red[t] += red[t + o]; __syncthreads(); }
    const float rs = rsqrtf(red[0] * (1.f / Dd) + 1e-5f);
    out[(size_t)b * Dd + t] = dy * rs * gamma[t] + beta[t];
}

// ---------------- launcher ----------------
extern "C" void kernel_launch(void* const* d_in, const int* in_sizes, int n_in,
                              void* d_out, int out_size) {
    const float* nf    = (const float*)d_in[0];
    // d_in[1] edge_weights, d_in[2] adj_matrix: dead for CLS-row output
    const float* masks = (const float*)d_in[3];
    const float* ct    = (const float*)d_in[4];
    const float* Wq    = (const float*)d_in[5];
    const float* bq    = (const float*)d_in[6];
    const float* Wk    = (const float*)d_in[7];
    const float* bk    = (const float*)d_in[8];
    const float* Wv    = (const float*)d_in[9];
    const float* bv    = (const float*)d_in[10];
    const float* Wo    = (const float*)d_in[11];
    const float* bo    = (const float*)d_in[12];
    const float* gamma = (const float*)d_in[13];
    const float* beta  = (const float*)d_in[14];
    float* out = (float*)d_out;

    k_prep   <<<dim3(Hh, 8), 512>>>(Wq, bq, Wk, bk, ct);
    k_scores <<<dim3(Nn / 16, Bx), 256>>>(nf, masks);
    k_softmax<<<32, 1024>>>();
    k_z      <<<dim3(ZCH, Bx), 256>>>(nf);
    k_red    <<<dim3(Bx, Hh, 4), 128>>>(ct);
    k_wv     <<<dim3(Hh, 8), 256>>>(Wv, bv);
    k_wo     <<<256, 256>>>(Wo, bo, ct);
    k_ln     <<<Bx, 512>>>(gamma, beta, out);
}